// round 3
// baseline (speedup 1.0000x reference)
#include <cuda_runtime.h>
#include <cstdint>

// ---------------------------------------------------------------------------
// Fused poker-feature + 2-layer MLP kernel, fp32 with packed f32x2 FMA.
//
//   out[B,256] = relu(x @ W1 + b1) @ W2 + b2
//   x = [hole(52) | board(52) | feats(15)]  -- first 104 cols are 0/1 bits
//
// Per block: 128 rows. Hidden dim processed in 8 chunks of 128 so the
// intermediate h never leaves shared memory. Stage 1 exploits sparsity
// (sum of ~6 W1 rows + 15 feature FMAs). Stage 2 is a classic smem GEMM
// with 8x8 micro-tiles using fma.rn.f32x2 (2 MACs/lane/instr).
// ---------------------------------------------------------------------------

#define BM        128
#define THREADS   512
#define IN_DIM    119
#define HIDDEN    1024
#define OUTD      256
#define NCHUNK    8       // 1024 / 128
#define HT_STRIDE 132     // 128 rows + 4 pad floats

// shared memory layout (float offsets)
#define HT_OFF    0
#define W1C_OFF   (128 * HT_STRIDE)          // 16896
#define B1C_OFF   (W1C_OFF + IN_DIM * 128)   // 32128
#define WS_OFF    (B1C_OFF + 128)            // 32256
#define FEAT_OFF  (WS_OFF + 32 * 256)        // 40448
#define CNT_OFF   (FEAT_OFF + 128 * 16)      // 42496
#define IDX_OFF   (CNT_OFF + 128)            // 42624 (bytes start here)
#define SMEM_BYTES (IDX_OFF * 4 + 128 * 104) // 183808 bytes

typedef unsigned long long u64;

__device__ __forceinline__ u64 dup2(float x) {
    unsigned u = __float_as_uint(x);
    u64 r;
    asm("mov.b64 %0, {%1, %2};" : "=l"(r) : "r"(u), "r"(u));
    return r;
}
__device__ __forceinline__ void ffma2(u64& d, u64 a, u64 b) {
    asm("fma.rn.f32x2 %0, %1, %2, %0;" : "+l"(d) : "l"(a), "l"(b));
}
__device__ __forceinline__ float2 unpk(u64 v) {
    unsigned lo, hi;
    asm("mov.b64 {%0, %1}, %2;" : "=r"(lo), "=r"(hi) : "l"(v));
    float2 f; f.x = __uint_as_float(lo); f.y = __uint_as_float(hi);
    return f;
}

// ---------------------------------------------------------------------------
// Per-row poker feature computation (matches reference exactly).
// ---------------------------------------------------------------------------
__device__ void compute_row_features(const float* __restrict__ hp,
                                     const float* __restrict__ bp,
                                     uint8_t* __restrict__ sidxr,
                                     int* __restrict__ cntOut,
                                     float* __restrict__ featOut)
{
    int cnt = 0;
    int bsc[4] = {0, 0, 0, 0};
    int asc[4] = {0, 0, 0, 0};
    int bcount = 0, hcount = 0;
    int pairs_b = 0, pairs_a = 0;
    bool trips_b = false, trips_a = false;
    int pb[17], pa[17];

#pragma unroll
    for (int rk = 0; rk < 13; rk++) {
        int b4 = 0, a4 = 0;
#pragma unroll
        for (int su = 0; su < 4; su++) {
            int c = rk * 4 + su;
            int hv = (hp[c] != 0.0f);
            int bv = (bp[c] != 0.0f);
            if (hv) sidxr[cnt++] = (uint8_t)c;
            if (bv) sidxr[cnt++] = (uint8_t)(52 + c);
            b4 += bv; a4 += hv + bv;
            bcount += bv; hcount += hv;
            bsc[su] += bv; asc[su] += hv + bv;
        }
        pairs_b += (b4 >= 2); trips_b |= (b4 >= 3);
        pairs_a += (a4 >= 2); trips_a |= (a4 >= 3);
        pb[rk] = (b4 > 0);
        pa[rk] = (a4 > 0);
    }
#pragma unroll
    for (int i = 13; i < 17; i++) { pb[i] = 0; pa[i] = 0; }

    float strength = trips_b ? 0.8f : (pairs_b >= 2 ? 0.6f : (pairs_b >= 1 ? 0.4f : 0.2f));
    if (bcount == 0) strength = 0.0f;

    int maxbsc = max(max(bsc[0], bsc[1]), max(bsc[2], bsc[3]));
    float flush_b = (maxbsc >= 3 && bcount > 0) ? 1.0f : 0.0f;

    bool sb = false;
#pragma unroll
    for (int j = 0; j < 13; j++) {
        int w = pb[j] + pb[j + 1] + pb[j + 2] + pb[j + 3] + pb[j + 4];
        if (w >= 3) sb = true;
    }
    float straight_b = (sb && bcount > 0) ? 1.0f : 0.0f;

    float g0 = (bcount == 0) ? 1.0f : 0.0f;
    float g3 = (bcount == 3) ? 1.0f : 0.0f;
    float g4 = (bcount == 4) ? 1.0f : 0.0f;
    float g5 = (bcount == 5) ? 1.0f : 0.0f;

    float valid = (hcount >= 2 && bcount >= 1) ? 1.0f : 0.0f;

    int msc = max(max(asc[0], asc[1]), max(asc[2], asc[3]));
    float flush_draw = (msc == 4) ? 1.0f : 0.0f;
    float flush_outs = fmaxf(0.0f, 13.0f - (float)msc) / 13.0f;

    bool found = false;
    int c4_at = 0;
#pragma unroll
    for (int j = 0; j < 13; j++) {
        int c5 = pa[j] + pa[j + 1] + pa[j + 2] + pa[j + 3] + pa[j + 4];
        bool q = (pa[j] > 0) && (c5 >= 4);
        if (q && !found) {
            found = true;
            c4_at = pa[j] + pa[j + 1] + pa[j + 2] + pa[j + 3];
        }
    }
    float sd = found ? 1.0f : 0.0f;
    float so = found ? (c4_at >= 4 ? 0.4f : 0.2f) : 0.0f;

    float total_outs = flush_draw * flush_outs * 9.0f + sd * so * 8.0f;
    float remaining = 52.0f - (float)(hcount + bcount);
    float equity = (remaining > 0.0f)
                       ? fminf(1.0f, total_outs / fmaxf(remaining, 1.0f))
                       : 0.0f;

    float hit_pair  = (pairs_a >= 1) ? 1.0f : 0.0f;
    float hit_trips = trips_a ? 1.0f : 0.0f;
    float hit_two   = (pairs_a >= 2) ? 1.0f : 0.0f;

    featOut[0]  = strength;
    featOut[1]  = flush_b;
    featOut[2]  = straight_b;
    featOut[3]  = g0;
    featOut[4]  = g3;
    featOut[5]  = g4;
    featOut[6]  = g5;
    featOut[7]  = valid * flush_draw;
    featOut[8]  = valid * flush_outs;
    featOut[9]  = valid * sd;
    featOut[10] = valid * so;
    featOut[11] = valid * equity;
    featOut[12] = valid * hit_pair;
    featOut[13] = valid * hit_trips;
    featOut[14] = valid * hit_two;
    *cntOut = cnt;
}

// ---------------------------------------------------------------------------
// Main fused kernel
// ---------------------------------------------------------------------------
__global__ void __launch_bounds__(THREADS, 1)
poker_mlp_kernel(const float* __restrict__ hole,
                 const float* __restrict__ board,
                 const float* __restrict__ W1,
                 const float* __restrict__ b1,
                 const float* __restrict__ W2,
                 const float* __restrict__ b2,
                 float* __restrict__ out,
                 int Btot)
{
    extern __shared__ float sm[];
    float*   sHT   = sm + HT_OFF;
    float*   sW1c  = sm + W1C_OFF;
    float*   sb1   = sm + B1C_OFF;
    float*   sws   = sm + WS_OFF;
    float*   sfeat = sm + FEAT_OFF;
    int*     scnt  = (int*)(sm + CNT_OFF);
    uint8_t* sidx  = (uint8_t*)(sm + IDX_OFF);

    const int tid  = threadIdx.x;
    const int row0 = blockIdx.x * BM;

    // ---- Phase 0: per-row features + sparse card index lists --------------
    if (tid < BM) {
        int r = tid;
        int grow = row0 + r;
        if (grow < Btot) {
            compute_row_features(hole + (size_t)grow * 52,
                                 board + (size_t)grow * 52,
                                 sidx + r * 104, &scnt[r], sfeat + r * 16);
        } else {
            scnt[r] = 0;
#pragma unroll
            for (int t = 0; t < 15; t++) sfeat[r * 16 + t] = 0.0f;
        }
    }
    __syncthreads();

    // ---- Stage-2 accumulators: 8 rows x 8 cols per thread (as 8x4 f32x2) --
    const int col_t = tid & 31;   // 32 col-threads: cols col_t*8 .. +8
    const int row_t = tid >> 5;   // 16 row-threads: rows row_t*8 .. +8
    u64 acc[8][4];
#pragma unroll
    for (int r = 0; r < 8; r++)
#pragma unroll
        for (int p = 0; p < 4; p++) acc[r][p] = 0ULL;

    const float4* W1c4 = (const float4*)sW1c;

    for (int chunk = 0; chunk < NCHUNK; chunk++) {
        // ---- stage W1 chunk (119x128) + b1 chunk into smem ----------------
        const int cb4 = chunk * 32;  // float4 column base
        for (int i = tid; i < IN_DIM * 32; i += THREADS) {
            int rw = i >> 5, c4 = i & 31;
            ((float4*)sW1c)[i] = ((const float4*)W1)[rw * 256 + cb4 + c4];
        }
        if (tid < 32)
            ((float4*)sb1)[tid] = ((const float4*)b1)[cb4 + tid];
        __syncthreads();

        // ---- Stage 1: h_chunk via sparse gather, stored transposed --------
        {
            const int j4 = tid & 31;  // float4 column within chunk
            const int rg = tid >> 5;  // 16 groups x 8 rows
            float4 bia = ((const float4*)sb1)[j4];
            for (int rr = 0; rr < 8; rr++) {
                int r = rg * 8 + rr;
                float4 a = bia;
                int cnt = scnt[r];
                const uint8_t* si = sidx + r * 104;
                for (int i = 0; i < cnt; i++) {
                    int ix = si[i];
                    float4 w = W1c4[ix * 32 + j4];
                    a.x += w.x; a.y += w.y; a.z += w.z; a.w += w.w;
                }
                const float* fr = sfeat + r * 16;
#pragma unroll
                for (int t = 0; t < 15; t++) {
                    float f = fr[t];
                    float4 w = W1c4[(104 + t) * 32 + j4];
                    a.x = fmaf(f, w.x, a.x);
                    a.y = fmaf(f, w.y, a.y);
                    a.z = fmaf(f, w.z, a.z);
                    a.w = fmaf(f, w.w, a.w);
                }
                a.x = fmaxf(a.x, 0.0f);
                a.y = fmaxf(a.y, 0.0f);
                a.z = fmaxf(a.z, 0.0f);
                a.w = fmaxf(a.w, 0.0f);
                int j = j4 * 4;
                sHT[(j + 0) * HT_STRIDE + r] = a.x;
                sHT[(j + 1) * HT_STRIDE + r] = a.y;
                sHT[(j + 2) * HT_STRIDE + r] = a.z;
                sHT[(j + 3) * HT_STRIDE + r] = a.w;
            }
        }
        __syncthreads();

        // ---- Stage 2: out += h_chunk @ W2_chunk, K-subtiles of 32 ---------
        for (int s = 0; s < 4; s++) {
            const int kbase = chunk * 128 + s * 32;
            for (int i = tid; i < 32 * 64; i += THREADS) {
                int k = i >> 6, n4 = i & 63;
                ((float4*)sws)[i] = ((const float4*)W2)[(kbase + k) * 64 + n4];
            }
            __syncthreads();

            const float* hbase = sHT + (s * 32) * HT_STRIDE + row_t * 8;
            const char*  wbase = (const char*)sws + col_t * 32;
#pragma unroll 4
            for (int kk = 0; kk < 32; kk++) {
                const float4* ap = (const float4*)(hbase + kk * HT_STRIDE);
                float4 a0 = ap[0];
                float4 a1 = ap[1];
                ulonglong2 w0 = *(const ulonglong2*)(wbase + kk * 1024);
                ulonglong2 w1 = *(const ulonglong2*)(wbase + kk * 1024 + 16);
                u64 ad[8];
                ad[0] = dup2(a0.x); ad[1] = dup2(a0.y);
                ad[2] = dup2(a0.z); ad[3] = dup2(a0.w);
                ad[4] = dup2(a1.x); ad[5] = dup2(a1.y);
                ad[6] = dup2(a1.z); ad[7] = dup2(a1.w);
#pragma unroll
                for (int r = 0; r < 8; r++) {
                    ffma2(acc[r][0], ad[r], w0.x);
                    ffma2(acc[r][1], ad[r], w0.y);
                    ffma2(acc[r][2], ad[r], w1.x);
                    ffma2(acc[r][3], ad[r], w1.y);
                }
            }
            __syncthreads();
        }
    }

    // ---- Epilogue: add b2, write out --------------------------------------
    const int col0 = col_t * 8;
    float4 bb0 = ((const float4*)b2)[col_t * 2];
    float4 bb1 = ((const float4*)b2)[col_t * 2 + 1];
#pragma unroll
    for (int rr = 0; rr < 8; rr++) {
        int grow = row0 + row_t * 8 + rr;
        if (grow >= Btot) continue;
        float2 p0 = unpk(acc[rr][0]);
        float2 p1 = unpk(acc[rr][1]);
        float2 p2 = unpk(acc[rr][2]);
        float2 p3 = unpk(acc[rr][3]);
        float4 o0 = make_float4(p0.x + bb0.x, p0.y + bb0.y,
                                p1.x + bb0.z, p1.y + bb0.w);
        float4 o1 = make_float4(p2.x + bb1.x, p2.y + bb1.y,
                                p3.x + bb1.z, p3.y + bb1.w);
        float4* op = (float4*)(out + (size_t)grow * OUTD + col0);
        op[0] = o0;
        op[1] = o1;
    }
}

// ---------------------------------------------------------------------------
extern "C" void kernel_launch(void* const* d_in, const int* in_sizes, int n_in,
                              void* d_out, int out_size)
{
    const float* hole  = (const float*)d_in[0];
    const float* board = (const float*)d_in[1];
    const float* W1    = (const float*)d_in[2];
    const float* b1    = (const float*)d_in[3];
    const float* W2    = (const float*)d_in[4];
    const float* b2    = (const float*)d_in[5];
    float* out = (float*)d_out;

    int B = in_sizes[0] / 52;
    int blocks = (B + BM - 1) / BM;

    cudaFuncSetAttribute(poker_mlp_kernel,
                         cudaFuncAttributeMaxDynamicSharedMemorySize,
                         SMEM_BYTES);
    poker_mlp_kernel<<<blocks, THREADS, SMEM_BYTES>>>(
        hole, board, W1, b1, W2, b2, out, B);
}